// round 2
// baseline (speedup 1.0000x reference)
#include <cuda_runtime.h>

#define NN 50000
#define IN_DIM 78
#define HEADS 10
#define CH 78
#define HC 780
#define EE 400000
#define E2 (EE + NN)     // 450000 edges incl self loops
#define BB 256
#define NEG 0.2f

// ---------------- scratch (static device memory; no allocs allowed) ----------------
__device__ float g_bufA[(size_t)NN * HC];   // xl, later reused as h2 (GCN gemm out)
__device__ float g_bufB[(size_t)NN * HC];   // xr, later reused as GCN aggregation out
__device__ float g_bufC[(size_t)NN * HC];   // GAT aggregation accum -> h1 (elu)
__device__ float g_score[(size_t)E2 * HEADS];
__device__ int   g_menc[(size_t)NN * HEADS];
__device__ float g_denom[(size_t)NN * HEADS];
__device__ int   g_deg[NN];
__device__ float g_dinv[NN];
__device__ int   g_cnt[BB];
__device__ int   g_flags[2];   // [0]=edge_index is int64, [1]=batch is int64

// ---------------- helpers ----------------
__device__ __forceinline__ int ld_idx(const void* p, long long i, int is64) {
    if (is64) return (int)((const long long*)p)[i];
    return ((const int*)p)[i];
}
// order-preserving float<->int encoding for atomicMax on signed int
__device__ __forceinline__ int fenc(float f) {
    int i = __float_as_int(f);
    return i >= 0 ? i : (i ^ 0x7fffffff);
}
__device__ __forceinline__ float fdec(int i) {
    return __int_as_float(i >= 0 ? i : (i ^ 0x7fffffff));
}

// ---------------- dtype detection ----------------
// If buffer is little-endian int64 with values in [0, 2^31), every odd int32
// word is 0. If int32, sampled odd words are node/batch ids (nonzero w.h.p.).
__global__ void detect_kernel(const void* ei, const void* batch) {
    int lane = threadIdx.x;  // 32 threads
    int nz_e = 0, nz_b = 0;
    for (int j = 0; j < 4; j++) {
        long long k = (long long)lane * 4 + j;             // 0..127
        long long p = (((2LL * EE - 2) * k) / 127) | 1;    // odd, < 2E
        if (((const int*)ei)[p] != 0) nz_e = 1;
        long long q = (long long)NN - 256 + 2 * k + 1;     // odd, in [NN-255, NN-1]
        if (((const int*)batch)[q] != 0) nz_b = 1;
    }
    nz_e = __any_sync(0xffffffffu, nz_e);
    nz_b = __any_sync(0xffffffffu, nz_b);
    if (lane == 0) {
        g_flags[0] = nz_e ? 0 : 1;
        g_flags[1] = nz_b ? 0 : 1;
    }
}

// ---------------- init: zero accumulators ----------------
__global__ void init_kernel(float* dout, int out_size) {
    int i = blockIdx.x * 256 + threadIdx.x;
    if (i < NN * HC) g_bufC[i] = 0.f;
    if (i < NN * HEADS) { g_denom[i] = 0.f; g_menc[i] = (int)0x80000000; }
    if (i < NN) g_deg[i] = 0;
    if (i < BB) g_cnt[i] = 0;
    if (i < out_size) dout[i] = 0.f;
}

__global__ void zeroB_kernel() {
    int i = blockIdx.x * 256 + threadIdx.x;
    if (i < NN * HC) g_bufB[i] = 0.f;
}

// ---------------- SGEMM: C[M,N] = A[M,K] @ B[K,N], row-major ----------------
#define BM 128
#define BN 128
#define BK 8
#define TM 8
#define TN 8
__global__ __launch_bounds__(256) void sgemm_kernel(
    const float* __restrict__ A, const float* __restrict__ B, float* __restrict__ C,
    int M, int N, int K)
{
    __shared__ float As[BK][BM];
    __shared__ float Bs[BK][BN];
    int tid = threadIdx.x;
    int row0 = blockIdx.y * BM;
    int col0 = blockIdx.x * BN;

    int aRow = tid >> 1;            // 0..127
    int aCol = (tid & 1) * 4;       // 0 or 4
    int bRow = tid >> 5;            // 0..7
    int bCol = (tid & 31) * 4;      // 0..124
    int tr = (tid >> 4) * TM;       // 0..120
    int tc = (tid & 15) * TN;       // 0..120

    float acc[TM][TN];
#pragma unroll
    for (int i = 0; i < TM; i++)
#pragma unroll
        for (int j = 0; j < TN; j++) acc[i][j] = 0.f;

    for (int k0 = 0; k0 < K; k0 += BK) {
#pragma unroll
        for (int j = 0; j < 4; j++) {
            int gr = row0 + aRow, gc = k0 + aCol + j;
            As[aCol + j][aRow] = (gr < M && gc < K) ? A[(long long)gr * K + gc] : 0.f;
        }
#pragma unroll
        for (int j = 0; j < 4; j++) {
            int gr = k0 + bRow, gc = col0 + bCol + j;
            Bs[bRow][bCol + j] = (gr < K && gc < N) ? B[(long long)gr * N + gc] : 0.f;
        }
        __syncthreads();
#pragma unroll
        for (int k = 0; k < BK; k++) {
            float ra[TM], rb[TN];
#pragma unroll
            for (int i = 0; i < TM; i++) ra[i] = As[k][tr + i];
#pragma unroll
            for (int j = 0; j < TN; j++) rb[j] = Bs[k][tc + j];
#pragma unroll
            for (int i = 0; i < TM; i++)
#pragma unroll
                for (int j = 0; j < TN; j++) acc[i][j] += ra[i] * rb[j];
        }
        __syncthreads();
    }
#pragma unroll
    for (int i = 0; i < TM; i++) {
        int gr = row0 + tr + i;
        if (gr >= M) break;
#pragma unroll
        for (int j = 0; j < TN; j++) {
            int gc = col0 + tc + j;
            if (gc < N) C[(long long)gr * N + gc] = acc[i][j];
        }
    }
}

// ---------------- GATv2 edge score + segment max (one warp per (edge, head)) ----------------
__global__ __launch_bounds__(256) void gat_score_kernel(const void* __restrict__ ei,
                                                        const float* __restrict__ att) {
    long long gtid = (long long)blockIdx.x * 256 + threadIdx.x;
    long long w = gtid >> 5;
    int lane = (int)(gtid & 31);
    if (w >= (long long)E2 * HEADS) return;
    int e = (int)(w / HEADS), h = (int)(w - (long long)e * HEADS);
    int is64 = g_flags[0];
    int src, dst;
    if (e < EE) { src = ld_idx(ei, e, is64); dst = ld_idx(ei, EE + e, is64); }
    else { src = dst = e - EE; }
    const float* pl = g_bufA + (size_t)src * HC + h * CH;
    const float* pr = g_bufB + (size_t)dst * HC + h * CH;
    const float* pa = att + h * CH;
    float s = 0.f;
    for (int c = lane; c < CH; c += 32) {
        float v = pl[c] + pr[c];
        v = v > 0.f ? v : NEG * v;       // leaky_relu
        s += v * pa[c];
    }
#pragma unroll
    for (int o = 16; o; o >>= 1) s += __shfl_xor_sync(0xffffffffu, s, o);
    if (lane == 0) {
        g_score[(size_t)e * HEADS + h] = s;
        atomicMax(&g_menc[dst * HEADS + h], fenc(s));
    }
}

// ---------------- exp(score - max) + segment sum ----------------
__global__ void gat_exp_kernel(const void* __restrict__ ei) {
    long long i = (long long)blockIdx.x * 256 + threadIdx.x;
    if (i >= (long long)E2 * HEADS) return;
    int e = (int)(i / HEADS), h = (int)(i - (long long)e * HEADS);
    int is64 = g_flags[0];
    int dst = (e < EE) ? ld_idx(ei, (long long)EE + e, is64) : e - EE;
    float ex = expf(g_score[i] - fdec(g_menc[dst * HEADS + h]));
    g_score[i] = ex;
    atomicAdd(&g_denom[dst * HEADS + h], ex);
}

// ---------------- GAT aggregation: bufC[dst] += alpha * xl[src] (float2) ----------------
__global__ void gat_agg_kernel(const void* __restrict__ ei) {
    const int PER = HC / 2;  // 390
    long long i = (long long)blockIdx.x * 256 + threadIdx.x;
    if (i >= (long long)E2 * PER) return;
    int e = (int)(i / PER);
    int r = (int)(i - (long long)e * PER) * 2;
    int h = r / CH;                         // 78 even -> pair never spans heads
    int is64 = g_flags[0];
    int src, dst;
    if (e < EE) { src = ld_idx(ei, e, is64); dst = ld_idx(ei, (long long)EE + e, is64); }
    else { src = dst = e - EE; }
    float alpha = g_score[(size_t)e * HEADS + h] / g_denom[dst * HEADS + h];
    float2 v = *(const float2*)(g_bufA + (size_t)src * HC + r);
    float* o = g_bufC + (size_t)dst * HC + r;
    atomicAdd(o, alpha * v.x);
    atomicAdd(o + 1, alpha * v.y);
}

// ---------------- h1 = elu(accum + bias1), in place ----------------
__global__ void elu_kernel(const float* __restrict__ bias1) {
    int i = blockIdx.x * 256 + threadIdx.x;
    if (i >= NN * HC) return;
    int c = i % HC;
    float v = g_bufC[i] + bias1[c];
    g_bufC[i] = v > 0.f ? v : expm1f(v);
}

// ---------------- GCN degree / norm ----------------
__global__ void deg_kernel(const void* __restrict__ ei) {
    int e = blockIdx.x * 256 + threadIdx.x;
    if (e >= E2) return;
    int is64 = g_flags[0];
    int dst = (e < EE) ? ld_idx(ei, (long long)EE + e, is64) : e - EE;
    atomicAdd(&g_deg[dst], 1);
}
__global__ void dinv_kernel() {
    int i = blockIdx.x * 256 + threadIdx.x;
    if (i >= NN) return;
    g_dinv[i] = rsqrtf(fmaxf((float)g_deg[i], 1e-12f));
}

// ---------------- GCN aggregation: bufB[dst] += norm * h2[src] (float4) ----------------
__global__ void gcn_agg_kernel(const void* __restrict__ ei) {
    const int PER = HC / 4;  // 195
    long long i = (long long)blockIdx.x * 256 + threadIdx.x;
    if (i >= (long long)E2 * PER) return;
    int e = (int)(i / PER);
    int r = (int)(i - (long long)e * PER) * 4;
    int is64 = g_flags[0];
    int src, dst;
    if (e < EE) { src = ld_idx(ei, e, is64); dst = ld_idx(ei, (long long)EE + e, is64); }
    else { src = dst = e - EE; }
    float norm = g_dinv[src] * g_dinv[dst];
    float4 v = *(const float4*)(g_bufA + (size_t)src * HC + r);
    float* o = g_bufB + (size_t)dst * HC + r;
    atomicAdd(o,     norm * v.x);
    atomicAdd(o + 1, norm * v.y);
    atomicAdd(o + 2, norm * v.z);
    atomicAdd(o + 3, norm * v.w);
}

// ---------------- pooling ----------------
__global__ void cnt_kernel(const void* __restrict__ batch) {
    int i = blockIdx.x * 256 + threadIdx.x;
    if (i >= NN) return;
    atomicAdd(&g_cnt[ld_idx(batch, i, g_flags[1])], 1);
}
__global__ void pool_kernel(const void* __restrict__ batch,
                            const float* __restrict__ bias_gcn, float* __restrict__ dout) {
    int i = blockIdx.x * 256 + threadIdx.x;
    if (i >= NN * HC) return;
    int node = i / HC, c = i - node * HC;
    float v = g_bufB[i] + bias_gcn[c];
    v = fmaxf(v, 0.f);                       // relu -> nonneg, so raw-bit int max is ordered
    int b = ld_idx(batch, node, g_flags[1]);
    atomicMax((int*)&dout[(size_t)b * 2 * HC + c], __float_as_int(v));
    atomicAdd(&dout[(size_t)b * 2 * HC + HC + c], v);
}
__global__ void final_kernel(float* __restrict__ dout) {
    int i = blockIdx.x * 256 + threadIdx.x;
    if (i >= BB * HC) return;
    int b = i / HC, c = i - b * HC;
    float cnt = fmaxf((float)g_cnt[b], 1.f);
    dout[(size_t)b * 2 * HC + HC + c] /= cnt;
}

// ---------------- launch ----------------
extern "C" void kernel_launch(void* const* d_in, const int* in_sizes, int n_in,
                              void* d_out, int out_size) {
    const float* x        = (const float*)d_in[0];
    const void*  ei       = d_in[1];
    const void*  batch    = d_in[2];
    const float* W_l      = (const float*)d_in[3];
    const float* W_r      = (const float*)d_in[4];
    const float* att      = (const float*)d_in[5];
    const float* bias1    = (const float*)d_in[6];
    const float* W_gcn    = (const float*)d_in[7];
    const float* bias_gcn = (const float*)d_in[8];
    float* out = (float*)d_out;

    float *pA, *pB, *pC;
    cudaGetSymbolAddress((void**)&pA, g_bufA);
    cudaGetSymbolAddress((void**)&pB, g_bufB);
    cudaGetSymbolAddress((void**)&pC, g_bufC);

    const int T = 256;
    detect_kernel<<<1, 32>>>(ei, batch);
    init_kernel<<<(NN * HC + T - 1) / T, T>>>(out, out_size);

    dim3 gmm((HC + BN - 1) / BN, (NN + BM - 1) / BM);   // (7, 391)
    sgemm_kernel<<<gmm, T>>>(x, W_l, pA, NN, HC, IN_DIM);   // xl
    sgemm_kernel<<<gmm, T>>>(x, W_r, pB, NN, HC, IN_DIM);   // xr

    long long nwarp_thr = (long long)E2 * HEADS * 32;
    gat_score_kernel<<<(unsigned)((nwarp_thr + T - 1) / T), T>>>(ei, att);
    long long neh = (long long)E2 * HEADS;
    gat_exp_kernel<<<(unsigned)((neh + T - 1) / T), T>>>(ei);
    long long nagg = (long long)E2 * (HC / 2);
    gat_agg_kernel<<<(unsigned)((nagg + T - 1) / T), T>>>(ei);
    elu_kernel<<<(NN * HC + T - 1) / T, T>>>(bias1);

    deg_kernel<<<(E2 + T - 1) / T, T>>>(ei);
    dinv_kernel<<<(NN + T - 1) / T, T>>>();

    sgemm_kernel<<<gmm, T>>>(pC, W_gcn, pA, NN, HC, HC);    // h2 = h1 @ W_gcn (into bufA)
    zeroB_kernel<<<(NN * HC + T - 1) / T, T>>>();           // bufB becomes GCN accum
    long long ngcn = (long long)E2 * (HC / 4);
    gcn_agg_kernel<<<(unsigned)((ngcn + T - 1) / T), T>>>(ei);

    cnt_kernel<<<(NN + T - 1) / T, T>>>(batch);
    pool_kernel<<<(NN * HC + T - 1) / T, T>>>(batch, bias_gcn, out);
    final_kernel<<<(BB * HC + T - 1) / T, T>>>(out);
}

// round 3
// speedup vs baseline: 1.6738x; 1.6738x over previous
#include <cuda_runtime.h>
#include <math.h>

#define NN 50000
#define IN_DIM 78
#define HEADS 10
#define CH 78
#define HC 780
#define HC2 390           // float2 slots per node row
#define EE 400000
#define E2 (EE + NN)      // 450000 edges incl self loops
#define BB 256
#define NEG 0.2f
#define NBLK 196          // ceil(NN/256)

// ---------------- scratch (static device memory; no allocs allowed) ----------------
__device__ float g_bufA[(size_t)NN * HC];   // xl -> (reused) h2 = h1 @ W_gcn
__device__ float g_bufB[(size_t)NN * HC];   // xr -> (reused) gcn output (relu'd)
__device__ float g_bufC[(size_t)NN * HC];   // h1 = elu(GAT out + bias1)
__device__ float g_score[(size_t)E2 * HEADS];
__device__ int   g_src[E2], g_dst[E2], g_csrc[E2];
__device__ int   g_deg[NN], g_fill[NN];
__device__ int   g_rowstart[NN + 1];
__device__ int   g_scan[NN];
__device__ int   g_bsum[256], g_boff[256];
__device__ float g_dinv[NN];
__device__ int   g_bstart[BB + 1];
__device__ int   g_flags[2];   // [0]=edge_index is int64, [1]=batch is int64

// ---------------- helpers ----------------
__device__ __forceinline__ int ld_idx(const void* p, long long i, int is64) {
    if (is64) return (int)((const long long*)p)[i];
    return ((const int*)p)[i];
}

// ---------------- dtype detection ----------------
__global__ void detect_kernel(const void* ei, const void* batch) {
    int lane = threadIdx.x;  // 32 threads
    int nz_e = 0, nz_b = 0;
    for (int j = 0; j < 4; j++) {
        long long k = (long long)lane * 4 + j;             // 0..127
        long long p = (((2LL * EE - 2) * k) / 127) | 1;    // odd, < 2E
        if (((const int*)ei)[p] != 0) nz_e = 1;
        long long q = (long long)NN - 256 + 2 * k + 1;     // odd, near end
        if (((const int*)batch)[q] != 0) nz_b = 1;
    }
    nz_e = __any_sync(0xffffffffu, nz_e);
    nz_b = __any_sync(0xffffffffu, nz_b);
    if (lane == 0) { g_flags[0] = nz_e ? 0 : 1; g_flags[1] = nz_b ? 0 : 1; }
}

// ---------------- init ----------------
__global__ void init_kernel() {
    int i = blockIdx.x * 256 + threadIdx.x;
    if (i < NN) { g_deg[i] = 0; g_fill[i] = 0; }
}

// ---------------- edge conversion + degree histogram ----------------
__global__ void conv_kernel(const void* __restrict__ ei) {
    int e = blockIdx.x * 256 + threadIdx.x;
    if (e >= E2) return;
    int is64 = g_flags[0];
    int s, d;
    if (e < EE) { s = ld_idx(ei, e, is64); d = ld_idx(ei, (long long)EE + e, is64); }
    else { s = d = e - EE; }
    g_src[e] = s; g_dst[e] = d;
    atomicAdd(&g_deg[d], 1);
}

// ---------------- prefix sum over degrees (3 kernels) ----------------
__global__ void scan1_kernel() {
    __shared__ int s[256];
    int i = blockIdx.x * 256 + threadIdx.x;
    int v = (i < NN) ? g_deg[i] : 0;
    s[threadIdx.x] = v;
    for (int off = 1; off < 256; off <<= 1) {
        __syncthreads();
        int t = (threadIdx.x >= off) ? s[threadIdx.x - off] : 0;
        __syncthreads();
        s[threadIdx.x] += t;
    }
    __syncthreads();
    if (i < NN) g_scan[i] = s[threadIdx.x];
    if (threadIdx.x == 255) g_bsum[blockIdx.x] = s[255];
}
__global__ void scan2_kernel() {
    __shared__ int s[256];
    int tid = threadIdx.x;
    int v = (tid < NBLK) ? g_bsum[tid] : 0;
    s[tid] = v;
    for (int off = 1; off < 256; off <<= 1) {
        __syncthreads();
        int t = (tid >= off) ? s[tid - off] : 0;
        __syncthreads();
        s[tid] += t;
    }
    __syncthreads();
    g_boff[tid] = s[tid] - v;   // exclusive
}
__global__ void scan3_kernel() {
    int i = blockIdx.x * 256 + threadIdx.x;
    if (i < NN) g_rowstart[i] = g_boff[i >> 8] + g_scan[i] - g_deg[i];
    if (i == 0) g_rowstart[NN] = E2;
}

__global__ void dinv_kernel() {
    int i = blockIdx.x * 256 + threadIdx.x;
    if (i >= NN) return;
    g_dinv[i] = rsqrtf(fmaxf((float)g_deg[i], 1e-12f));
}

// ---------------- CSR scatter ----------------
__global__ void scatter_kernel() {
    int e = blockIdx.x * 256 + threadIdx.x;
    if (e >= E2) return;
    int d = g_dst[e];
    int pos = g_rowstart[d] + atomicAdd(&g_fill[d], 1);
    g_csrc[pos] = g_src[e];
}

// ---------------- SGEMM: C[M,N] = A[M,K] @ B[K,N], row-major ----------------
#define BM 128
#define BN 128
#define BK 8
#define TM 8
#define TN 8
__global__ __launch_bounds__(256) void sgemm_kernel(
    const float* __restrict__ A, const float* __restrict__ B, float* __restrict__ C,
    int M, int N, int K)
{
    __shared__ float As[BK][BM];
    __shared__ float Bs[BK][BN];
    int tid = threadIdx.x;
    int row0 = blockIdx.y * BM;
    int col0 = blockIdx.x * BN;

    int aRow = tid >> 1;
    int aCol = (tid & 1) * 4;
    int bRow = tid >> 5;
    int bCol = (tid & 31) * 4;
    int tr = (tid >> 4) * TM;
    int tc = (tid & 15) * TN;

    float acc[TM][TN];
#pragma unroll
    for (int i = 0; i < TM; i++)
#pragma unroll
        for (int j = 0; j < TN; j++) acc[i][j] = 0.f;

    for (int k0 = 0; k0 < K; k0 += BK) {
#pragma unroll
        for (int j = 0; j < 4; j++) {
            int gr = row0 + aRow, gc = k0 + aCol + j;
            As[aCol + j][aRow] = (gr < M && gc < K) ? A[(long long)gr * K + gc] : 0.f;
        }
#pragma unroll
        for (int j = 0; j < 4; j++) {
            int gr = k0 + bRow, gc = col0 + bCol + j;
            Bs[bRow][bCol + j] = (gr < K && gc < N) ? B[(long long)gr * N + gc] : 0.f;
        }
        __syncthreads();
#pragma unroll
        for (int k = 0; k < BK; k++) {
            float ra[TM], rb[TN];
#pragma unroll
            for (int i = 0; i < TM; i++) ra[i] = As[k][tr + i];
#pragma unroll
            for (int j = 0; j < TN; j++) rb[j] = Bs[k][tc + j];
#pragma unroll
            for (int i = 0; i < TM; i++)
#pragma unroll
                for (int j = 0; j < TN; j++) acc[i][j] += ra[i] * rb[j];
        }
        __syncthreads();
    }
#pragma unroll
    for (int i = 0; i < TM; i++) {
        int gr = row0 + tr + i;
        if (gr >= M) break;
#pragma unroll
        for (int j = 0; j < TN; j++) {
            int gc = col0 + tc + j;
            if (gc < N) C[(long long)gr * N + gc] = acc[i][j];
        }
    }
}

// ---------------- fused GATv2: warp per destination node ----------------
// pass A: per in-edge scores (head-chunked, warp reduce)
// softmax stats on lanes 0..9; pass B: weighted gather; epilogue: +bias, elu
__global__ __launch_bounds__(256) void gat_kernel(const float* __restrict__ att,
                                                  const float* __restrict__ bias1) {
    __shared__ float2 attS[HC2];
    int tid = threadIdx.x;
    for (int i = tid; i < HC2; i += 256) attS[i] = ((const float2*)att)[i];
    __syncthreads();

    int dst = blockIdx.x * 8 + (tid >> 5);
    if (dst >= NN) return;
    int lane = tid & 31;
    int p0 = g_rowstart[dst], p1 = g_rowstart[dst + 1];

    const float2* xl2 = (const float2*)g_bufA;
    const float2* xr2 = (const float2*)g_bufB;
    size_t dbase = (size_t)dst * HC2;

    // xr[dst] resident in registers (head-chunked: slot lane, and 32+lane for lane<7)
    float2 xr0[HEADS], xr1[HEADS];
#pragma unroll
    for (int h = 0; h < HEADS; h++) {
        xr0[h] = xr2[dbase + h * 39 + lane];
        if (lane < 7) xr1[h] = xr2[dbase + h * 39 + 32 + lane];
    }

    // ---- pass A: scores ----
    for (int p = p0; p < p1; p++) {
        int src = g_csrc[p];
        size_t sb = (size_t)src * HC2;
        float sc = 0.f;
#pragma unroll
        for (int h = 0; h < HEADS; h++) {
            float2 v = xl2[sb + h * 39 + lane];
            float2 a = attS[h * 39 + lane];
            float e0 = v.x + xr0[h].x; e0 = e0 > 0.f ? e0 : NEG * e0;
            float e1 = v.y + xr0[h].y; e1 = e1 > 0.f ? e1 : NEG * e1;
            float t = e0 * a.x + e1 * a.y;
            if (lane < 7) {
                float2 v1 = xl2[sb + h * 39 + 32 + lane];
                float2 a1 = attS[h * 39 + 32 + lane];
                float f0 = v1.x + xr1[h].x; f0 = f0 > 0.f ? f0 : NEG * f0;
                float f1 = v1.y + xr1[h].y; f1 = f1 > 0.f ? f1 : NEG * f1;
                t += f0 * a1.x + f1 * a1.y;
            }
#pragma unroll
            for (int o = 16; o; o >>= 1) t += __shfl_xor_sync(0xffffffffu, t, o);
            if (lane == h) sc = t;
        }
        if (lane < HEADS) g_score[(size_t)p * HEADS + lane] = sc;
    }

    // ---- softmax stats (lane h owns head h) ----
    float m = -3.4e38f, rden = 0.f;
    if (lane < HEADS) {
        for (int p = p0; p < p1; p++) m = fmaxf(m, g_score[(size_t)p * HEADS + lane]);
        float ssum = 0.f;
        for (int p = p0; p < p1; p++) ssum += expf(g_score[(size_t)p * HEADS + lane] - m);
        rden = 1.f / ssum;
    }

    // ---- pass B: weighted aggregation ----
    float2 acc0[HEADS], acc1[HEADS];
#pragma unroll
    for (int h = 0; h < HEADS; h++) { acc0[h] = make_float2(0.f, 0.f); acc1[h] = make_float2(0.f, 0.f); }
    for (int p = p0; p < p1; p++) {
        int src = g_csrc[p];
        size_t sb = (size_t)src * HC2;
        float a = (lane < HEADS) ? expf(g_score[(size_t)p * HEADS + lane] - m) * rden : 0.f;
#pragma unroll
        for (int h = 0; h < HEADS; h++) {
            float al = __shfl_sync(0xffffffffu, a, h);
            float2 v = xl2[sb + h * 39 + lane];
            acc0[h].x += al * v.x; acc0[h].y += al * v.y;
            if (lane < 7) {
                float2 v1 = xl2[sb + h * 39 + 32 + lane];
                acc1[h].x += al * v1.x; acc1[h].y += al * v1.y;
            }
        }
    }

    // ---- epilogue: h1 = elu(acc + bias1) ----
    float2* o2 = (float2*)g_bufC;
    const float2* b2 = (const float2*)bias1;
#pragma unroll
    for (int h = 0; h < HEADS; h++) {
        int j = h * 39 + lane;
        float2 bb = b2[j];
        float u0 = acc0[h].x + bb.x; u0 = u0 > 0.f ? u0 : expm1f(u0);
        float u1 = acc0[h].y + bb.y; u1 = u1 > 0.f ? u1 : expm1f(u1);
        o2[dbase + j] = make_float2(u0, u1);
        if (lane < 7) {
            int j1 = h * 39 + 32 + lane;
            float2 bb1 = b2[j1];
            float w0 = acc1[h].x + bb1.x; w0 = w0 > 0.f ? w0 : expm1f(w0);
            float w1 = acc1[h].y + bb1.y; w1 = w1 > 0.f ? w1 : expm1f(w1);
            o2[dbase + j1] = make_float2(w0, w1);
        }
    }
}

// ---------------- fused GCN: warp per destination node (+bias, relu) ----------------
__global__ __launch_bounds__(256) void gcn_kernel(const float* __restrict__ bias_gcn) {
    int dst = blockIdx.x * 8 + (threadIdx.x >> 5);
    if (dst >= NN) return;
    int lane = threadIdx.x & 31;
    int p0 = g_rowstart[dst], p1 = g_rowstart[dst + 1];
    float di = g_dinv[dst];
    const float2* h2 = (const float2*)g_bufA;

    float2 acc[13];
#pragma unroll
    for (int k = 0; k < 13; k++) acc[k] = make_float2(0.f, 0.f);

    for (int p = p0; p < p1; p++) {
        int src = g_csrc[p];
        float nrm = di * g_dinv[src];
        size_t sb = (size_t)src * HC2;
#pragma unroll
        for (int k = 0; k < 13; k++) {
            int idx = lane + 32 * k;
            if (idx < HC2) {
                float2 v = h2[sb + idx];
                acc[k].x += nrm * v.x; acc[k].y += nrm * v.y;
            }
        }
    }
    float2* o2 = (float2*)g_bufB;
    const float2* b2 = (const float2*)bias_gcn;
    size_t dbase = (size_t)dst * HC2;
#pragma unroll
    for (int k = 0; k < 13; k++) {
        int idx = lane + 32 * k;
        if (idx < HC2) {
            float2 bb = b2[idx];
            o2[dbase + idx] = make_float2(fmaxf(acc[k].x + bb.x, 0.f),
                                          fmaxf(acc[k].y + bb.y, 0.f));
        }
    }
}

// ---------------- batch segment boundaries (batch is sorted) ----------------
__global__ void bstart_kernel(const void* __restrict__ batch) {
    int i = blockIdx.x * 256 + threadIdx.x;
    if (i >= NN) return;
    int is64 = g_flags[1];
    int b = ld_idx(batch, i, is64);
    if (i == 0) { for (int bb = 0; bb <= b; bb++) g_bstart[bb] = 0; }
    else {
        int pb = ld_idx(batch, i - 1, is64);
        for (int bb = pb + 1; bb <= b; bb++) g_bstart[bb] = i;
    }
    if (i == NN - 1) { for (int bb = b + 1; bb <= BB; bb++) g_bstart[bb] = NN; }
}

// ---------------- segmented pooling: block per batch ----------------
__global__ __launch_bounds__(256) void pool_kernel(float* __restrict__ out) {
    int b = blockIdx.x;
    int tid = threadIdx.x;
    int lo = g_bstart[b], hi = g_bstart[b + 1];
    float inv = 1.f / fmaxf((float)(hi - lo), 1.f);
    for (int c = tid; c < HC; c += 256) {
        float mx = 0.f, sm = 0.f;
        for (int n = lo; n < hi; n++) {
            float v = g_bufB[(size_t)n * HC + c];
            mx = fmaxf(mx, v);
            sm += v;
        }
        out[(size_t)b * 2 * HC + c] = mx;
        out[(size_t)b * 2 * HC + HC + c] = sm * inv;
    }
}

// ---------------- launch ----------------
extern "C" void kernel_launch(void* const* d_in, const int* in_sizes, int n_in,
                              void* d_out, int out_size) {
    const float* x        = (const float*)d_in[0];
    const void*  ei       = d_in[1];
    const void*  batch    = d_in[2];
    const float* W_l      = (const float*)d_in[3];
    const float* W_r      = (const float*)d_in[4];
    const float* att      = (const float*)d_in[5];
    const float* bias1    = (const float*)d_in[6];
    const float* W_gcn    = (const float*)d_in[7];
    const float* bias_gcn = (const float*)d_in[8];
    float* out = (float*)d_out;

    float *pA, *pB, *pC;
    cudaGetSymbolAddress((void**)&pA, g_bufA);
    cudaGetSymbolAddress((void**)&pB, g_bufB);
    cudaGetSymbolAddress((void**)&pC, g_bufC);

    const int T = 256;
    const int GE = (E2 + T - 1) / T;     // 1758
    const int GN = NBLK;                 // 196

    detect_kernel<<<1, 32>>>(ei, batch);
    init_kernel<<<GN, T>>>();
    conv_kernel<<<GE, T>>>(ei);
    scan1_kernel<<<GN, T>>>();
    scan2_kernel<<<1, T>>>();
    scan3_kernel<<<GN, T>>>();
    dinv_kernel<<<GN, T>>>();
    scatter_kernel<<<GE, T>>>();

    dim3 gmm((HC + BN - 1) / BN, (NN + BM - 1) / BM);   // (7, 391)
    sgemm_kernel<<<gmm, T>>>(x, W_l, pA, NN, HC, IN_DIM);   // xl -> bufA
    sgemm_kernel<<<gmm, T>>>(x, W_r, pB, NN, HC, IN_DIM);   // xr -> bufB

    gat_kernel<<<(NN * 32) / T, T>>>(att, bias1);           // h1 -> bufC

    sgemm_kernel<<<gmm, T>>>(pC, W_gcn, pA, NN, HC, HC);    // h2 -> bufA

    gcn_kernel<<<(NN * 32) / T, T>>>(bias_gcn);             // relu(gcn) -> bufB

    bstart_kernel<<<GN, T>>>(batch);
    pool_kernel<<<BB, T>>>(out);
}

// round 8
// speedup vs baseline: 2.0990x; 1.2541x over previous
#include <cuda_runtime.h>
#include <math.h>
#include <mma.h>
using namespace nvcuda;

#define NN 50000
#define IN_DIM 78
#define HEADS 10
#define CH 78
#define HC 780
#define HC2 390           // float2 slots per node row
#define EE 400000
#define E2 (EE + NN)      // 450000 edges incl self loops
#define BB 256
#define NEG 0.2f
#define NBLK 196          // ceil(NN/256)

// ---------------- scratch (static device memory; no allocs allowed) ----------------
__device__ float g_bufA[(size_t)NN * HC];   // xl -> (reused) h2 = h1 @ W_gcn
__device__ float g_bufB[(size_t)NN * HC];   // xr -> (reused) gcn output (relu'd)
__device__ float g_bufC[(size_t)NN * HC];   // h1 = elu(GAT out + bias1)
__device__ float g_score[(size_t)E2 * HEADS];
__device__ int   g_src[E2], g_dst[E2], g_csrc[E2];
__device__ int   g_deg[NN], g_fill[NN];
__device__ int   g_rowstart[NN + 1];
__device__ int   g_scan[NN];
__device__ int   g_bsum[256], g_boff[256];
__device__ float g_dinv[NN];
__device__ int   g_bstart[BB + 1];
__device__ int   g_flags[2];   // [0]=edge_index is int64, [1]=batch is int64

// ---------------- helpers ----------------
__device__ __forceinline__ int ld_idx(const void* p, long long i, int is64) {
    if (is64) return (int)((const long long*)p)[i];
    return ((const int*)p)[i];
}

// ---------------- dtype detection ----------------
__global__ void detect_kernel(const void* ei, const void* batch) {
    int lane = threadIdx.x;  // 32 threads
    int nz_e = 0, nz_b = 0;
    for (int j = 0; j < 4; j++) {
        long long k = (long long)lane * 4 + j;             // 0..127
        long long p = (((2LL * EE - 2) * k) / 127) | 1;    // odd, < 2E
        if (((const int*)ei)[p] != 0) nz_e = 1;
        long long q = (long long)NN - 256 + 2 * k + 1;     // odd, near end
        if (((const int*)batch)[q] != 0) nz_b = 1;
    }
    nz_e = __any_sync(0xffffffffu, nz_e);
    nz_b = __any_sync(0xffffffffu, nz_b);
    if (lane == 0) { g_flags[0] = nz_e ? 0 : 1; g_flags[1] = nz_b ? 0 : 1; }
}

// ---------------- init ----------------
__global__ void init_kernel() {
    int i = blockIdx.x * 256 + threadIdx.x;
    if (i < NN) { g_deg[i] = 0; g_fill[i] = 0; }
}

// ---------------- edge conversion + degree histogram ----------------
__global__ void conv_kernel(const void* __restrict__ ei) {
    int e = blockIdx.x * 256 + threadIdx.x;
    if (e >= E2) return;
    int is64 = g_flags[0];
    int s, d;
    if (e < EE) { s = ld_idx(ei, e, is64); d = ld_idx(ei, (long long)EE + e, is64); }
    else { s = d = e - EE; }
    g_src[e] = s; g_dst[e] = d;
    atomicAdd(&g_deg[d], 1);
}

// ---------------- prefix sum over degrees (3 kernels) ----------------
__global__ void scan1_kernel() {
    __shared__ int s[256];
    int i = blockIdx.x * 256 + threadIdx.x;
    int v = (i < NN) ? g_deg[i] : 0;
    s[threadIdx.x] = v;
    for (int off = 1; off < 256; off <<= 1) {
        __syncthreads();
        int t = (threadIdx.x >= off) ? s[threadIdx.x - off] : 0;
        __syncthreads();
        s[threadIdx.x] += t;
    }
    __syncthreads();
    if (i < NN) g_scan[i] = s[threadIdx.x];
    if (threadIdx.x == 255) g_bsum[blockIdx.x] = s[255];
}
__global__ void scan2_kernel() {
    __shared__ int s[256];
    int tid = threadIdx.x;
    int v = (tid < NBLK) ? g_bsum[tid] : 0;
    s[tid] = v;
    for (int off = 1; off < 256; off <<= 1) {
        __syncthreads();
        int t = (tid >= off) ? s[tid - off] : 0;
        __syncthreads();
        s[tid] += t;
    }
    __syncthreads();
    g_boff[tid] = s[tid] - v;   // exclusive
}
__global__ void scan3_kernel() {
    int i = blockIdx.x * 256 + threadIdx.x;
    if (i < NN) g_rowstart[i] = g_boff[i >> 8] + g_scan[i] - g_deg[i];
    if (i == 0) g_rowstart[NN] = E2;
}

__global__ void dinv_kernel() {
    int i = blockIdx.x * 256 + threadIdx.x;
    if (i >= NN) return;
    g_dinv[i] = rsqrtf(fmaxf((float)g_deg[i], 1e-12f));
}

// ---------------- CSR scatter ----------------
__global__ void scatter_kernel() {
    int e = blockIdx.x * 256 + threadIdx.x;
    if (e >= E2) return;
    int d = g_dst[e];
    int pos = g_rowstart[d] + atomicAdd(&g_fill[d], 1);
    g_csrc[pos] = g_src[e];
}

// ---------------- TF32 tensor-core GEMM: C[M,N] = A[M,K] @ B[K,N], row-major ----------------
// 128x128 block tile, BK=32, 8 warps in 4(M)x2(N) grid, warp tile 32x64 (2x4 wmma frags)
#define GBM 128
#define GBN 128
#define GBK 32
__global__ __launch_bounds__(256) void tf32gemm_kernel(
    const float* __restrict__ A, const float* __restrict__ B, float* __restrict__ C,
    int M, int N, int K)
{
    __shared__ float As[GBM][GBK + 4];   // 128x36
    __shared__ float Bs[GBK][GBN + 4];   // 32x132
    __shared__ float stage[8][16][20];   // per-warp partial-tile staging

    int tid = threadIdx.x;
    int wid = tid >> 5;
    int lane = tid & 31;
    int row0 = blockIdx.y * GBM, col0 = blockIdx.x * GBN;
    int wm = (wid >> 1) * 32;   // warp M offset within block tile
    int wn = (wid & 1) * 64;    // warp N offset

    wmma::fragment<wmma::accumulator, 16, 16, 8, float> acc[2][4];
#pragma unroll
    for (int i = 0; i < 2; i++)
#pragma unroll
        for (int j = 0; j < 4; j++) wmma::fill_fragment(acc[i][j], 0.0f);

    for (int k0 = 0; k0 < K; k0 += GBK) {
        // load A tile: 128x32
#pragma unroll
        for (int it = 0; it < (GBM * GBK) / 256; it++) {
            int idx = it * 256 + tid;
            int r = idx >> 5, c = idx & 31;
            int gr = row0 + r, gc = k0 + c;
            As[r][c] = (gr < M && gc < K) ? A[(long long)gr * K + gc] : 0.f;
        }
        // load B tile: 32x128
#pragma unroll
        for (int it = 0; it < (GBK * GBN) / 256; it++) {
            int idx = it * 256 + tid;
            int r = idx >> 7, c = idx & 127;
            int gr = k0 + r, gc = col0 + c;
            Bs[r][c] = (gr < K && gc < N) ? B[(long long)gr * N + gc] : 0.f;
        }
        __syncthreads();

#pragma unroll
        for (int kk = 0; kk < GBK / 8; kk++) {
            wmma::fragment<wmma::matrix_a, 16, 16, 8, wmma::precision::tf32, wmma::row_major> af[2];
            wmma::fragment<wmma::matrix_b, 16, 16, 8, wmma::precision::tf32, wmma::row_major> bf[4];
#pragma unroll
            for (int i = 0; i < 2; i++) {
                wmma::load_matrix_sync(af[i], &As[wm + 16 * i][kk * 8], GBK + 4);
#pragma unroll
                for (int t = 0; t < af[i].num_elements; t++)
                    af[i].x[t] = wmma::__float_to_tf32(af[i].x[t]);
            }
#pragma unroll
            for (int j = 0; j < 4; j++) {
                wmma::load_matrix_sync(bf[j], &Bs[kk * 8][wn + 16 * j], GBN + 4);
#pragma unroll
                for (int t = 0; t < bf[j].num_elements; t++)
                    bf[j].x[t] = wmma::__float_to_tf32(bf[j].x[t]);
            }
#pragma unroll
            for (int i = 0; i < 2; i++)
#pragma unroll
                for (int j = 0; j < 4; j++)
                    wmma::mma_sync(acc[i][j], af[i], bf[j], acc[i][j]);
        }
        __syncthreads();
    }

    // store
    if (row0 + GBM <= M && col0 + GBN <= N) {
#pragma unroll
        for (int i = 0; i < 2; i++)
#pragma unroll
            for (int j = 0; j < 4; j++)
                wmma::store_matrix_sync(&C[(long long)(row0 + wm + 16 * i) * N + col0 + wn + 16 * j],
                                        acc[i][j], N, wmma::mem_row_major);
    } else {
#pragma unroll
        for (int i = 0; i < 2; i++)
#pragma unroll
            for (int j = 0; j < 4; j++) {
                wmma::store_matrix_sync(&stage[wid][0][0], acc[i][j], 20, wmma::mem_row_major);
                __syncwarp();
                int r0 = row0 + wm + 16 * i, c0 = col0 + wn + 16 * j;
                for (int t = lane; t < 256; t += 32) {
                    int r = t >> 4, c = t & 15;
                    if (r0 + r < M && c0 + c < N)
                        C[(long long)(r0 + r) * N + c0 + c] = stage[wid][r][c];
                }
                __syncwarp();
            }
    }
}

// ---------------- fused GATv2: warp per destination node ----------------
__global__ __launch_bounds__(256) void gat_kernel(const float* __restrict__ att,
                                                  const float* __restrict__ bias1) {
    __shared__ float2 attS[HC2];
    int tid = threadIdx.x;
    for (int i = tid; i < HC2; i += 256) attS[i] = ((const float2*)att)[i];
    __syncthreads();

    int dst = blockIdx.x * 8 + (tid >> 5);
    if (dst >= NN) return;
    int lane = tid & 31;
    int p0 = g_rowstart[dst], p1 = g_rowstart[dst + 1];

    const float2* xl2 = (const float2*)g_bufA;
    const float2* xr2 = (const float2*)g_bufB;
    size_t dbase = (size_t)dst * HC2;

    float2 xr0[HEADS], xr1[HEADS];
#pragma unroll
    for (int h = 0; h < HEADS; h++) {
        xr0[h] = xr2[dbase + h * 39 + lane];
        if (lane < 7) xr1[h] = xr2[dbase + h * 39 + 32 + lane];
    }

    // ---- pass A: scores ----
    for (int p = p0; p < p1; p++) {
        int src = g_csrc[p];
        size_t sb = (size_t)src * HC2;
        float sc = 0.f;
#pragma unroll
        for (int h = 0; h < HEADS; h++) {
            float2 v = xl2[sb + h * 39 + lane];
            float2 a = attS[h * 39 + lane];
            float e0 = v.x + xr0[h].x; e0 = e0 > 0.f ? e0 : NEG * e0;
            float e1 = v.y + xr0[h].y; e1 = e1 > 0.f ? e1 : NEG * e1;
            float t = e0 * a.x + e1 * a.y;
            if (lane < 7) {
                float2 v1 = xl2[sb + h * 39 + 32 + lane];
                float2 a1 = attS[h * 39 + 32 + lane];
                float f0 = v1.x + xr1[h].x; f0 = f0 > 0.f ? f0 : NEG * f0;
                float f1 = v1.y + xr1[h].y; f1 = f1 > 0.f ? f1 : NEG * f1;
                t += f0 * a1.x + f1 * a1.y;
            }
#pragma unroll
            for (int o = 16; o; o >>= 1) t += __shfl_xor_sync(0xffffffffu, t, o);
            if (lane == h) sc = t;
        }
        if (lane < HEADS) g_score[(size_t)p * HEADS + lane] = sc;
    }

    // ---- softmax stats (lane h owns head h) ----
    float m = -3.4e38f, rden = 0.f;
    if (lane < HEADS) {
        for (int p = p0; p < p1; p++) m = fmaxf(m, g_score[(size_t)p * HEADS + lane]);
        float ssum = 0.f;
        for (int p = p0; p < p1; p++) ssum += expf(g_score[(size_t)p * HEADS + lane] - m);
        rden = 1.f / ssum;
    }

    // ---- pass B: weighted aggregation ----
    float2 acc0[HEADS], acc1[HEADS];
#pragma unroll
    for (int h = 0; h < HEADS; h++) { acc0[h] = make_float2(0.f, 0.f); acc1[h] = make_float2(0.f, 0.f); }
    for (int p = p0; p < p1; p++) {
        int src = g_csrc[p];
        size_t sb = (size_t)src * HC2;
        float a = (lane < HEADS) ? expf(g_score[(size_t)p * HEADS + lane] - m) * rden : 0.f;
#pragma unroll
        for (int h = 0; h < HEADS; h++) {
            float al = __shfl_sync(0xffffffffu, a, h);
            float2 v = xl2[sb + h * 39 + lane];
            acc0[h].x += al * v.x; acc0[h].y += al * v.y;
            if (lane < 7) {
                float2 v1 = xl2[sb + h * 39 + 32 + lane];
                acc1[h].x += al * v1.x; acc1[h].y += al * v1.y;
            }
        }
    }

    // ---- epilogue: h1 = elu(acc + bias1) ----
    float2* o2 = (float2*)g_bufC;
    const float2* b2 = (const float2*)bias1;
#pragma unroll
    for (int h = 0; h < HEADS; h++) {
        int j = h * 39 + lane;
        float2 bb = b2[j];
        float u0 = acc0[h].x + bb.x; u0 = u0 > 0.f ? u0 : expm1f(u0);
        float u1 = acc0[h].y + bb.y; u1 = u1 > 0.f ? u1 : expm1f(u1);
        o2[dbase + j] = make_float2(u0, u1);
        if (lane < 7) {
            int j1 = h * 39 + 32 + lane;
            float2 bb1 = b2[j1];
            float w0 = acc1[h].x + bb1.x; w0 = w0 > 0.f ? w0 : expm1f(w0);
            float w1 = acc1[h].y + bb1.y; w1 = w1 > 0.f ? w1 : expm1f(w1);
            o2[dbase + j1] = make_float2(w0, w1);
        }
    }
}

// ---------------- fused GCN: warp per destination node (+bias, relu) ----------------
__global__ __launch_bounds__(256) void gcn_kernel(const float* __restrict__ bias_gcn) {
    int dst = blockIdx.x * 8 + (threadIdx.x >> 5);
    if (dst >= NN) return;
    int lane = threadIdx.x & 31;
    int p0 = g_rowstart[dst], p1 = g_rowstart[dst + 1];
    float di = g_dinv[dst];
    const float2* h2 = (const float2*)g_bufA;

    float2 acc[13];
#pragma unroll
    for (int k = 0; k < 13; k++) acc[k] = make_float2(0.f, 0.f);

    for (int p = p0; p < p1; p++) {
        int src = g_csrc[p];
        float nrm = di * g_dinv[src];
        size_t sb = (size_t)src * HC2;
#pragma unroll
        for (int k = 0; k < 13; k++) {
            int idx = lane + 32 * k;
            if (idx < HC2) {
                float2 v = h2[sb + idx];
                acc[k].x += nrm * v.x; acc[k].y += nrm * v.y;
            }
        }
    }
    float2* o2 = (float2*)g_bufB;
    const float2* b2 = (const float2*)bias_gcn;
    size_t dbase = (size_t)dst * HC2;
#pragma unroll
    for (int k = 0; k < 13; k++) {
        int idx = lane + 32 * k;
        if (idx < HC2) {
            float2 bb = b2[idx];
            o2[dbase + idx] = make_float2(fmaxf(acc[k].x + bb.x, 0.f),
                                          fmaxf(acc[k].y + bb.y, 0.f));
        }
    }
}

// ---------------- batch segment boundaries (batch is sorted) ----------------
__global__ void bstart_kernel(const void* __restrict__ batch) {
    int i = blockIdx.x * 256 + threadIdx.x;
    if (i >= NN) return;
    int is64 = g_flags[1];
    int b = ld_idx(batch, i, is64);
    if (i == 0) { for (int bb = 0; bb <= b; bb++) g_bstart[bb] = 0; }
    else {
        int pb = ld_idx(batch, i - 1, is64);
        for (int bb = pb + 1; bb <= b; bb++) g_bstart[bb] = i;
    }
    if (i == NN - 1) { for (int bb = b + 1; bb <= BB; bb++) g_bstart[bb] = NN; }
}

// ---------------- segmented pooling: block per batch ----------------
__global__ __launch_bounds__(256) void pool_kernel(float* __restrict__ out) {
    int b = blockIdx.x;
    int tid = threadIdx.x;
    int lo = g_bstart[b], hi = g_bstart[b + 1];
    float inv = 1.f / fmaxf((float)(hi - lo), 1.f);
    for (int c = tid; c < HC; c += 256) {
        float mx = 0.f, sm = 0.f;
        for (int n = lo; n < hi; n++) {
            float v = g_bufB[(size_t)n * HC + c];
            mx = fmaxf(mx, v);
            sm += v;
        }
        out[(size_t)b * 2 * HC + c] = mx;
        out[(size_t)b * 2 * HC + HC + c] = sm * inv;
    }
}

// ---------------- launch ----------------
extern "C" void kernel_launch(void* const* d_in, const int* in_sizes, int n_in,
                              void* d_out, int out_size) {
    const float* x        = (const float*)d_in[0];
    const void*  ei       = d_in[1];
    const void*  batch    = d_in[2];
    const float* W_l      = (const float*)d_in[3];
    const float* W_r      = (const float*)d_in[4];
    const float* att      = (const float*)d_in[5];
    const float* bias1    = (const float*)d_in[6];
    const float* W_gcn    = (const float*)d_in[7];
    const float* bias_gcn = (const float*)d_in[8];
    float* out = (float*)d_out;

    float *pA, *pB, *pC;
    cudaGetSymbolAddress((void**)&pA, g_bufA);
    cudaGetSymbolAddress((void**)&pB, g_bufB);
    cudaGetSymbolAddress((void**)&pC, g_bufC);

    const int T = 256;
    const int GE = (E2 + T - 1) / T;
    const int GN = NBLK;

    detect_kernel<<<1, 32>>>(ei, batch);
    init_kernel<<<GN, T>>>();
    conv_kernel<<<GE, T>>>(ei);
    scan1_kernel<<<GN, T>>>();
    scan2_kernel<<<1, T>>>();
    scan3_kernel<<<GN, T>>>();
    dinv_kernel<<<GN, T>>>();
    scatter_kernel<<<GE, T>>>();

    dim3 gmm((HC + GBN - 1) / GBN, (NN + GBM - 1) / GBM);   // (7, 391)
    tf32gemm_kernel<<<gmm, T>>>(x, W_l, pA, NN, HC, IN_DIM);   // xl -> bufA
    tf32gemm_kernel<<<gmm, T>>>(x, W_r, pB, NN, HC, IN_DIM);   // xr -> bufB

    gat_kernel<<<(NN * 32) / T, T>>>(att, bias1);              // h1 -> bufC

    tf32gemm_kernel<<<gmm, T>>>(pC, W_gcn, pA, NN, HC, HC);    // h2 -> bufA

    gcn_kernel<<<(NN * 32) / T, T>>>(bias_gcn);                // relu(gcn) -> bufB

    bstart_kernel<<<GN, T>>>(batch);
    pool_kernel<<<BB, T>>>(out);
}